// round 2
// baseline (speedup 1.0000x reference)
#include <cuda_runtime.h>
#include <math.h>

#define B_ROWS 16384
#define D_COLS 4096
#define H1N 64
#define H2N 32
#define BD_TOT (16384.0*4096.0)

typedef unsigned long long u64;

// ---------------- scratch (device globals, no allocations) ----------------
__device__ float  d_srow[B_ROWS];
__device__ float  d_med;
__device__ double d_nsum[2];                 // sum(norm), sum(norm^2)
__device__ float  d_G[B_ROWS * H1N];         // norm_raw @ W_in
__device__ double d_s1[H1N], d_q1[H1N];      // col stats of G
__device__ float  d_H2[B_ROWS * H2N];        // h1 @ W_enc + b_enc
__device__ double d_s2[H2N], d_q2[H2N];
__device__ float  d_H3[B_ROWS * H1N];        // h2 @ W_dec + b_dec
__device__ double d_s3[H1N], d_q3[H1N];

// ---------------- packed f32x2 helpers (Blackwell FFMA2 path) -------------
__device__ __forceinline__ u64 pk2(float lo, float hi) {
    u64 r; asm("mov.b64 %0, {%1,%2};" : "=l"(r) : "f"(lo), "f"(hi)); return r;
}
__device__ __forceinline__ void fma2(u64 &c, u64 a, u64 b) {
    asm("fma.rn.f32x2 %0, %1, %2, %0;" : "+l"(c) : "l"(a), "l"(b));
}
__device__ __forceinline__ float2 unpk2(u64 v) {
    float2 o; asm("mov.b64 {%0,%1}, %2;" : "=f"(o.x), "=f"(o.y) : "l"(v)); return o;
}

// ---------------- K0: zero the accumulators --------------------------------
__global__ void k_zero() {
    int t = threadIdx.x;
    if (t < 2)   d_nsum[t] = 0.0;
    if (t < H1N) { d_s1[t] = 0.0; d_q1[t] = 0.0; d_s3[t] = 0.0; d_q3[t] = 0.0; }
    if (t < H2N) { d_s2[t] = 0.0; d_q2[t] = 0.0; }
}

// ---------------- K1: per-row sums of x ------------------------------------
__global__ __launch_bounds__(256) void k_rowsum(const float* __restrict__ x) {
    int b = blockIdx.x;
    const float4* row = (const float4*)(x + (size_t)b * D_COLS);
    float s = 0.f;
#pragma unroll
    for (int i = 0; i < 4; i++) {
        float4 v = row[threadIdx.x + i * 256];
        s += (v.x + v.y) + (v.z + v.w);
    }
#pragma unroll
    for (int o = 16; o > 0; o >>= 1) s += __shfl_down_sync(0xffffffffu, s, o);
    __shared__ float ws[8];
    if ((threadIdx.x & 31) == 0) ws[threadIdx.x >> 5] = s;
    __syncthreads();
    if (threadIdx.x == 0) {
        float t = 0.f;
#pragma unroll
        for (int i = 0; i < 8; i++) t += ws[i];
        d_srow[b] = t;
    }
}

// ---------------- K2: lower median via bitonic sort (1 block) --------------
__global__ void k_median() {
    extern __shared__ float sm[];
    int tid = threadIdx.x;
    for (int i = tid; i < B_ROWS; i += 1024) sm[i] = d_srow[i];
    __syncthreads();
    for (int k = 2; k <= B_ROWS; k <<= 1) {
        for (int j = k >> 1; j > 0; j >>= 1) {
            for (int i = tid; i < B_ROWS; i += 1024) {
                int ixj = i ^ j;
                if (ixj > i) {
                    float a = sm[i], b = sm[ixj];
                    bool up = ((i & k) == 0);
                    if ((a > b) == up) { sm[i] = b; sm[ixj] = a; }
                }
            }
            __syncthreads();
        }
    }
    if (tid == 0) d_med = sm[(B_ROWS - 1) / 2];
}

// ---------------- K3: fused norm + GEMM1 + global stats --------------------
// G = norm_raw @ W_in   (norm_raw = log(x * med/srow + 1), computed on the fly)
// BM=32 rows/block, N=64 cols, K-chunks of 64. 128 threads.
__global__ __launch_bounds__(128) void k_gemm1(const float* __restrict__ x,
                                               const float* __restrict__ Win) {
    __shared__ float  rfac[32];
    __shared__ float  As[32][68];
    __shared__ float  Ws[64 * 64];
    __shared__ double red[256];
    int tid = threadIdx.x;
    int r0  = blockIdx.x * 32;
    if (tid < 32) rfac[tid] = d_med / d_srow[r0 + tid];
    __syncthreads();

    int tr = tid >> 4, tc = tid & 15;
    u64 acc[4][2];
#pragma unroll
    for (int i = 0; i < 4; i++) { acc[i][0] = 0ULL; acc[i][1] = 0ULL; }
    double dsum = 0.0, dsq = 0.0;
    int lrow = tid >> 2, lk = (tid & 3) * 16;

    for (int kk = 0; kk < D_COLS; kk += 64) {
        // load W_in chunk (contiguous 64 rows x 64 cols)
#pragma unroll
        for (int i = 0; i < 8; i++) {
            int idx = (tid + i * 128) * 4;
            *(float4*)&Ws[idx] = *(const float4*)&Win[(size_t)kk * 64 + idx];
        }
        // load x chunk, compute norm on the fly, accumulate stats
        float rf = rfac[lrow];
        float ls = 0.f, lq = 0.f;
        const float* xp = x + (size_t)(r0 + lrow) * D_COLS + kk + lk;
#pragma unroll
        for (int j = 0; j < 4; j++) {
            float4 v = *(const float4*)(xp + j * 4);
            float n0 = __logf(fmaf(v.x, rf, 1.f));
            float n1 = __logf(fmaf(v.y, rf, 1.f));
            float n2 = __logf(fmaf(v.z, rf, 1.f));
            float n3 = __logf(fmaf(v.w, rf, 1.f));
            ls += (n0 + n1) + (n2 + n3);
            lq += fmaf(n0, n0, n1 * n1) + fmaf(n2, n2, n3 * n3);
            *(float4*)&As[lrow][lk + j * 4] = make_float4(n0, n1, n2, n3);
        }
        dsum += ls; dsq += lq;
        __syncthreads();
#pragma unroll 8
        for (int k = 0; k < 64; k++) {
            float4 w = *(const float4*)&Ws[k * 64 + tc * 4];
            u64 b0 = pk2(w.x, w.y), b1 = pk2(w.z, w.w);
#pragma unroll
            for (int i = 0; i < 4; i++) {
                float av = As[tr * 4 + i][k];
                u64 a2 = pk2(av, av);
                fma2(acc[i][0], a2, b0);
                fma2(acc[i][1], a2, b1);
            }
        }
        __syncthreads();
    }
#pragma unroll
    for (int i = 0; i < 4; i++) {
        float2 p0 = unpk2(acc[i][0]), p1 = unpk2(acc[i][1]);
        *(float4*)&d_G[(size_t)(r0 + tr * 4 + i) * 64 + tc * 4] =
            make_float4(p0.x, p0.y, p1.x, p1.y);
    }
    red[tid] = dsum; red[128 + tid] = dsq;
    __syncthreads();
    for (int s = 64; s > 0; s >>= 1) {
        if (tid < s) { red[tid] += red[tid + s]; red[128 + tid] += red[128 + tid + s]; }
        __syncthreads();
    }
    if (tid == 0) {
        atomicAdd(&d_nsum[0], red[0]);
        atomicAdd(&d_nsum[1], red[128]);
    }
}

// ---------------- K4: column stats of G ------------------------------------
__global__ __launch_bounds__(256) void k_colstatsG() {
    int col = threadIdx.x & 63, rg = threadIdx.x >> 6;  // 4 row-groups
    int r0 = blockIdx.x * 256;
    double s = 0.0, q = 0.0;
    for (int r = rg; r < 256; r += 4) {
        float v = d_G[(size_t)(r0 + r) * 64 + col];
        s += (double)v; q += (double)v * (double)v;
    }
    __shared__ double sh[256], shq[256];
    sh[threadIdx.x] = s; shq[threadIdx.x] = q;
    __syncthreads();
    if (rg == 0) {
#pragma unroll
        for (int g = 1; g < 4; g++) { s += sh[col + 64 * g]; q += shq[col + 64 * g]; }
        atomicAdd(&d_s1[col], s);
        atomicAdd(&d_q1[col], q);
    }
}

// ---------------- K5: layer-1 BN+ReLU -> h1 @ W_enc + b_enc (+stats) -------
__global__ __launch_bounds__(256) void k_mlp2(const float* __restrict__ g1,
                                              const float* __restrict__ bt1,
                                              const float* __restrict__ Wenc,
                                              const float* __restrict__ benc) {
    __shared__ float mu1[64], sc1[64], bts[64];
    __shared__ float We[64 * 32];
    __shared__ float be[32];
    __shared__ float h1buf[8][64];
    int tid = threadIdx.x;
    if (tid < 64) {
        double tot = d_nsum[0], totq = d_nsum[1];
        double sigma2 = (totq - tot * tot / BD_TOT) / (BD_TOT - 1.0);   // ddof=1
        double mu  = d_s1[tid] / 16384.0;
        double var = d_q1[tid] / 16384.0 - mu * mu;                     // biased
        mu1[tid] = (float)mu;
        sc1[tid] = g1[tid] * (float)rsqrt(var + 1e-5 * sigma2);
        bts[tid] = bt1[tid];
    }
    for (int i = tid; i < 64 * 32; i += 256) We[i] = Wenc[i];
    if (tid < 32) be[tid] = benc[tid];
    __syncthreads();

    int w = tid >> 5, lane = tid & 31;
    int rbase = blockIdx.x * 64 + w * 8;
    float ls = 0.f, lq = 0.f;
    for (int rr = 0; rr < 8; rr++) {
        int row = rbase + rr;
        float a0 = d_G[(size_t)row * 64 + lane];
        float a1 = d_G[(size_t)row * 64 + 32 + lane];
        h1buf[w][lane]      = fmaxf(fmaf(a0 - mu1[lane],      sc1[lane],      bts[lane]),      0.f);
        h1buf[w][32 + lane] = fmaxf(fmaf(a1 - mu1[32 + lane], sc1[32 + lane], bts[32 + lane]), 0.f);
        __syncwarp();
        float acc = be[lane];
#pragma unroll
        for (int k = 0; k < 64; k++) acc = fmaf(h1buf[w][k], We[k * 32 + lane], acc);
        d_H2[(size_t)row * 32 + lane] = acc;
        ls += acc; lq += acc * acc;
        __syncwarp();
    }
    atomicAdd(&d_s2[lane], (double)ls);
    atomicAdd(&d_q2[lane], (double)lq);
}

// ---------------- K6: layer-2 BN+ReLU -> h2 @ W_dec + b_dec (+stats) -------
__global__ __launch_bounds__(256) void k_mlp3(const float* __restrict__ g2,
                                              const float* __restrict__ bt2,
                                              const float* __restrict__ Wdec,
                                              const float* __restrict__ bdec) {
    __shared__ float mu2[32], sc2[32], bts[32];
    __shared__ float Wd[32 * 64];
    __shared__ float bd[64];
    __shared__ float h2buf[8][32];
    int tid = threadIdx.x;
    if (tid < 32) {
        double mu  = d_s2[tid] / 16384.0;
        double var = d_q2[tid] / 16384.0 - mu * mu;
        mu2[tid] = (float)mu;
        sc2[tid] = g2[tid] * (float)rsqrt(var + 1e-5);
        bts[tid] = bt2[tid];
    }
    for (int i = tid; i < 32 * 64; i += 256) Wd[i] = Wdec[i];
    if (tid < 64) bd[tid] = bdec[tid];
    __syncthreads();

    int w = tid >> 5, lane = tid & 31;
    int rbase = blockIdx.x * 64 + w * 8;
    float ls0 = 0.f, lq0 = 0.f, ls1 = 0.f, lq1 = 0.f;
    for (int rr = 0; rr < 8; rr++) {
        int row = rbase + rr;
        float v = d_H2[(size_t)row * 32 + lane];
        h2buf[w][lane] = fmaxf(fmaf(v - mu2[lane], sc2[lane], bts[lane]), 0.f);
        __syncwarp();
        float acc0 = bd[lane], acc1 = bd[32 + lane];
#pragma unroll
        for (int k = 0; k < 32; k++) {
            float h = h2buf[w][k];
            acc0 = fmaf(h, Wd[k * 64 + lane],      acc0);
            acc1 = fmaf(h, Wd[k * 64 + 32 + lane], acc1);
        }
        d_H3[(size_t)row * 64 + lane]      = acc0;
        d_H3[(size_t)row * 64 + 32 + lane] = acc1;
        ls0 += acc0; lq0 += acc0 * acc0;
        ls1 += acc1; lq1 += acc1 * acc1;
        __syncwarp();
    }
    atomicAdd(&d_s3[lane],      (double)ls0);
    atomicAdd(&d_q3[lane],      (double)lq0);
    atomicAdd(&d_s3[32 + lane], (double)ls1);
    atomicAdd(&d_q3[32 + lane], (double)lq1);
}

// ---------------- K7: BN3+ReLU -> h3 @ {W_pi,W_m,W_th} + act ---------------
// BM=64 x BN=128 tile, full K=64 resident, blockIdx.z picks head.
__global__ __launch_bounds__(256) void k_out(const float* __restrict__ g3,
                                             const float* __restrict__ bt3,
                                             const float* __restrict__ Wpi,
                                             const float* __restrict__ bpi,
                                             const float* __restrict__ Wm,
                                             const float* __restrict__ bm,
                                             const float* __restrict__ Wth,
                                             const float* __restrict__ bth,
                                             float* __restrict__ out) {
    extern __shared__ float sd[];
    float* h3s = sd;                 // 64*64
    float* Ws  = sd + 4096;          // 64*128
    float* mu3 = Ws + 8192;          // 64
    float* sc3 = mu3 + 64;           // 64
    float* bts = sc3 + 64;           // 64
    float* bs  = bts + 64;           // 128
    int tid = threadIdx.x;
    int mz  = blockIdx.z;
    const float* W  = (mz == 0) ? Wpi : ((mz == 1) ? Wm : Wth);
    const float* bb = (mz == 0) ? bpi : ((mz == 1) ? bm : bth);
    int c0 = blockIdx.x * 128, r0 = blockIdx.y * 64;

    if (tid < 64) {
        double mu  = d_s3[tid] / 16384.0;
        double var = d_q3[tid] / 16384.0 - mu * mu;
        mu3[tid] = (float)mu;
        sc3[tid] = g3[tid] * (float)rsqrt(var + 1e-5);
        bts[tid] = bt3[tid];
    }
    if (tid < 128) bs[tid] = bb[c0 + tid];
    __syncthreads();

    {   // load h3 tile (BN+ReLU applied)
        int lr = tid >> 2, lk = (tid & 3) * 16;
        const float4* src = (const float4*)&d_H3[(size_t)(r0 + lr) * 64 + lk];
#pragma unroll
        for (int j = 0; j < 4; j++) {
            float4 v = src[j];
            int c = lk + j * 4;
            v.x = fmaxf(fmaf(v.x - mu3[c + 0], sc3[c + 0], bts[c + 0]), 0.f);
            v.y = fmaxf(fmaf(v.y - mu3[c + 1], sc3[c + 1], bts[c + 1]), 0.f);
            v.z = fmaxf(fmaf(v.z - mu3[c + 2], sc3[c + 2], bts[c + 2]), 0.f);
            v.w = fmaxf(fmaf(v.w - mu3[c + 3], sc3[c + 3], bts[c + 3]), 0.f);
            *(float4*)&h3s[lr * 64 + c] = v;
        }
        // load W tile (64 x 128)
#pragma unroll
        for (int i = 0; i < 8; i++) {
            int idx = tid + i * 256;            // 0..2047 float4s
            int kk = idx >> 5, cc = (idx & 31) * 4;
            *(float4*)&Ws[kk * 128 + cc] = *(const float4*)&W[(size_t)kk * 4096 + c0 + cc];
        }
    }
    __syncthreads();

    int tr = tid >> 4, tc = tid & 15;
    u64 acc[4][4];
#pragma unroll
    for (int i = 0; i < 4; i++)
#pragma unroll
        for (int p = 0; p < 4; p++) acc[i][p] = 0ULL;

#pragma unroll 16
    for (int k = 0; k < 64; k++) {
        float4 w0 = *(const float4*)&Ws[k * 128 + tc * 4];
        float4 w1 = *(const float4*)&Ws[k * 128 + 64 + tc * 4];
        u64 b0 = pk2(w0.x, w0.y), b1 = pk2(w0.z, w0.w);
        u64 b2 = pk2(w1.x, w1.y), b3 = pk2(w1.z, w1.w);
#pragma unroll
        for (int i = 0; i < 4; i++) {
            float av = h3s[(tr * 4 + i) * 64 + k];
            u64 a2 = pk2(av, av);
            fma2(acc[i][0], a2, b0);
            fma2(acc[i][1], a2, b1);
            fma2(acc[i][2], a2, b2);
            fma2(acc[i][3], a2, b3);
        }
    }

    size_t obase = (size_t)mz * (size_t)B_ROWS * D_COLS + (size_t)r0 * D_COLS + c0;
#pragma unroll
    for (int i = 0; i < 4; i++) {
        int row = tr * 4 + i;
        float2 p0 = unpk2(acc[i][0]), p1 = unpk2(acc[i][1]);
        float2 p2 = unpk2(acc[i][2]), p3 = unpk2(acc[i][3]);
        float z[8] = { p0.x + bs[tc * 4 + 0], p0.y + bs[tc * 4 + 1],
                       p1.x + bs[tc * 4 + 2], p1.y + bs[tc * 4 + 3],
                       p2.x + bs[64 + tc * 4 + 0], p2.y + bs[64 + tc * 4 + 1],
                       p3.x + bs[64 + tc * 4 + 2], p3.y + bs[64 + tc * 4 + 3] };
#pragma unroll
        for (int j = 0; j < 8; j++) {
            z[j] = (mz == 0) ? __fdividef(1.f, 1.f + __expf(-z[j])) : __expf(z[j]);
        }
        *(float4*)&out[obase + (size_t)row * D_COLS + tc * 4]      = make_float4(z[0], z[1], z[2], z[3]);
        *(float4*)&out[obase + (size_t)row * D_COLS + 64 + tc * 4] = make_float4(z[4], z[5], z[6], z[7]);
    }
}

// ---------------- launch ----------------------------------------------------
extern "C" void kernel_launch(void* const* d_in, const int* in_sizes, int n_in,
                              void* d_out, int out_size) {
    const float* x    = (const float*)d_in[0];
    const float* Win  = (const float*)d_in[1];
    /* b_in = d_in[2] cancels inside BatchNorm — unused */
    const float* g1   = (const float*)d_in[3];
    const float* bt1  = (const float*)d_in[4];
    const float* Wenc = (const float*)d_in[5];
    const float* benc = (const float*)d_in[6];
    const float* g2   = (const float*)d_in[7];
    const float* bt2  = (const float*)d_in[8];
    const float* Wdec = (const float*)d_in[9];
    const float* bdec = (const float*)d_in[10];
    const float* g3   = (const float*)d_in[11];
    const float* bt3  = (const float*)d_in[12];
    const float* Wpi  = (const float*)d_in[13];
    const float* bpi  = (const float*)d_in[14];
    const float* Wm   = (const float*)d_in[15];
    const float* bm   = (const float*)d_in[16];
    const float* Wth  = (const float*)d_in[17];
    const float* bth  = (const float*)d_in[18];
    float* out = (float*)d_out;

    cudaFuncSetAttribute(k_median, cudaFuncAttributeMaxDynamicSharedMemorySize, 65536);
    cudaFuncSetAttribute(k_out,    cudaFuncAttributeMaxDynamicSharedMemorySize, 50432);

    k_zero<<<1, 64>>>();
    k_rowsum<<<B_ROWS, 256>>>(x);
    k_median<<<1, 1024, 65536>>>();
    k_gemm1<<<B_ROWS / 32, 128>>>(x, Win);
    k_colstatsG<<<64, 256>>>();
    k_mlp2<<<B_ROWS / 64, 256>>>(g1, bt1, Wenc, benc);
    k_mlp3<<<B_ROWS / 64, 256>>>(g2, bt2, Wdec, bdec);
    dim3 g(D_COLS / 128, B_ROWS / 64, 3);
    k_out<<<g, 256, 50432>>>(g3, bt3, Wpi, bpi, Wm, bm, Wth, bth, out);
}

// round 3
// speedup vs baseline: 1.1751x; 1.1751x over previous
#include <cuda_runtime.h>
#include <math.h>

#define B_ROWS 16384
#define D_COLS 4096
#define H1N 64
#define H2N 32
#define BD_TOT (16384.0*4096.0)

typedef unsigned long long u64;
typedef unsigned int u32;

// ---------------- scratch (device globals, no allocations) ----------------
__device__ float  d_srow[B_ROWS];
__device__ float  d_med;
__device__ double d_nsum[2];                 // sum(norm), sum(norm^2)
__device__ float  d_G[B_ROWS * H1N];         // norm_raw @ W_in
__device__ double d_s1[H1N], d_q1[H1N];      // col stats of G
__device__ float  d_H2[B_ROWS * H2N];        // h1 @ W_enc + b_enc
__device__ double d_s2[H2N], d_q2[H2N];
__device__ float  d_H3[B_ROWS * H1N];        // h2 @ W_dec + b_dec
__device__ double d_s3[H1N], d_q3[H1N];

// ---------------- packed f32x2 helpers (Blackwell FFMA2 path) -------------
__device__ __forceinline__ u64 pk2(float lo, float hi) {
    u64 r; asm("mov.b64 %0, {%1,%2};" : "=l"(r) : "f"(lo), "f"(hi)); return r;
}
__device__ __forceinline__ void fma2(u64 &c, u64 a, u64 b) {
    asm("fma.rn.f32x2 %0, %1, %2, %0;" : "+l"(c) : "l"(a), "l"(b));
}
__device__ __forceinline__ float2 unpk2(u64 v) {
    float2 o; asm("mov.b64 {%0,%1}, %2;" : "=f"(o.x), "=f"(o.y) : "l"(v)); return o;
}

// ---------------- tf32 mma helpers -----------------------------------------
__device__ __forceinline__ u32 to_tf32(float f) {
    u32 u; asm("cvt.rna.tf32.f32 %0, %1;" : "=r"(u) : "f"(f)); return u;
}
__device__ __forceinline__ void mma1688(float c[4], const u32 a[4], const u32 b[2]) {
    asm volatile(
        "mma.sync.aligned.m16n8k8.row.col.f32.tf32.tf32.f32 "
        "{%0,%1,%2,%3},{%4,%5,%6,%7},{%8,%9},{%0,%1,%2,%3};"
        : "+f"(c[0]), "+f"(c[1]), "+f"(c[2]), "+f"(c[3])
        : "r"(a[0]), "r"(a[1]), "r"(a[2]), "r"(a[3]), "r"(b[0]), "r"(b[1]));
}

// ---------------- K0: zero the accumulators --------------------------------
__global__ void k_zero() {
    int t = threadIdx.x;
    if (t < 2)   d_nsum[t] = 0.0;
    if (t < H1N) { d_s1[t] = 0.0; d_q1[t] = 0.0; d_s3[t] = 0.0; d_q3[t] = 0.0; }
    if (t < H2N) { d_s2[t] = 0.0; d_q2[t] = 0.0; }
}

// ---------------- K1: per-row sums of x ------------------------------------
__global__ __launch_bounds__(256) void k_rowsum(const float* __restrict__ x) {
    int b = blockIdx.x;
    const float4* row = (const float4*)(x + (size_t)b * D_COLS);
    float s = 0.f;
#pragma unroll
    for (int i = 0; i < 4; i++) {
        float4 v = row[threadIdx.x + i * 256];
        s += (v.x + v.y) + (v.z + v.w);
    }
#pragma unroll
    for (int o = 16; o > 0; o >>= 1) s += __shfl_down_sync(0xffffffffu, s, o);
    __shared__ float ws[8];
    if ((threadIdx.x & 31) == 0) ws[threadIdx.x >> 5] = s;
    __syncthreads();
    if (threadIdx.x == 0) {
        float t = 0.f;
#pragma unroll
        for (int i = 0; i < 8; i++) t += ws[i];
        d_srow[b] = t;
    }
}

// ---------------- K2: lower median via bitonic sort (1 block) --------------
__global__ void k_median() {
    extern __shared__ float sm[];
    int tid = threadIdx.x;
    for (int i = tid; i < B_ROWS; i += 1024) sm[i] = d_srow[i];
    __syncthreads();
    for (int k = 2; k <= B_ROWS; k <<= 1) {
        for (int j = k >> 1; j > 0; j >>= 1) {
            for (int i = tid; i < B_ROWS; i += 1024) {
                int ixj = i ^ j;
                if (ixj > i) {
                    float a = sm[i], b = sm[ixj];
                    bool up = ((i & k) == 0);
                    if ((a > b) == up) { sm[i] = b; sm[ixj] = a; }
                }
            }
            __syncthreads();
        }
    }
    if (tid == 0) d_med = sm[(B_ROWS - 1) / 2];
}

// ---------------- K3: fused norm + GEMM1 + global stats --------------------
__global__ __launch_bounds__(128) void k_gemm1(const float* __restrict__ x,
                                               const float* __restrict__ Win) {
    __shared__ float  rfac[32];
    __shared__ float  As[32][68];
    __shared__ float  Ws[64 * 64];
    __shared__ double red[256];
    int tid = threadIdx.x;
    int r0  = blockIdx.x * 32;
    if (tid < 32) rfac[tid] = d_med / d_srow[r0 + tid];
    __syncthreads();

    int tr = tid >> 4, tc = tid & 15;
    u64 acc[4][2];
#pragma unroll
    for (int i = 0; i < 4; i++) { acc[i][0] = 0ULL; acc[i][1] = 0ULL; }
    double dsum = 0.0, dsq = 0.0;
    int lrow = tid >> 2, lk = (tid & 3) * 16;

    for (int kk = 0; kk < D_COLS; kk += 64) {
#pragma unroll
        for (int i = 0; i < 8; i++) {
            int idx = (tid + i * 128) * 4;
            *(float4*)&Ws[idx] = *(const float4*)&Win[(size_t)kk * 64 + idx];
        }
        float rf = rfac[lrow];
        float ls = 0.f, lq = 0.f;
        const float* xp = x + (size_t)(r0 + lrow) * D_COLS + kk + lk;
#pragma unroll
        for (int j = 0; j < 4; j++) {
            float4 v = *(const float4*)(xp + j * 4);
            float n0 = __logf(fmaf(v.x, rf, 1.f));
            float n1 = __logf(fmaf(v.y, rf, 1.f));
            float n2 = __logf(fmaf(v.z, rf, 1.f));
            float n3 = __logf(fmaf(v.w, rf, 1.f));
            ls += (n0 + n1) + (n2 + n3);
            lq += fmaf(n0, n0, n1 * n1) + fmaf(n2, n2, n3 * n3);
            *(float4*)&As[lrow][lk + j * 4] = make_float4(n0, n1, n2, n3);
        }
        dsum += ls; dsq += lq;
        __syncthreads();
#pragma unroll 8
        for (int k = 0; k < 64; k++) {
            float4 w = *(const float4*)&Ws[k * 64 + tc * 4];
            u64 b0 = pk2(w.x, w.y), b1 = pk2(w.z, w.w);
#pragma unroll
            for (int i = 0; i < 4; i++) {
                float av = As[tr * 4 + i][k];
                u64 a2 = pk2(av, av);
                fma2(acc[i][0], a2, b0);
                fma2(acc[i][1], a2, b1);
            }
        }
        __syncthreads();
    }
#pragma unroll
    for (int i = 0; i < 4; i++) {
        float2 p0 = unpk2(acc[i][0]), p1 = unpk2(acc[i][1]);
        *(float4*)&d_G[(size_t)(r0 + tr * 4 + i) * 64 + tc * 4] =
            make_float4(p0.x, p0.y, p1.x, p1.y);
    }
    red[tid] = dsum; red[128 + tid] = dsq;
    __syncthreads();
    for (int s = 64; s > 0; s >>= 1) {
        if (tid < s) { red[tid] += red[tid + s]; red[128 + tid] += red[128 + tid + s]; }
        __syncthreads();
    }
    if (tid == 0) {
        atomicAdd(&d_nsum[0], red[0]);
        atomicAdd(&d_nsum[1], red[128]);
    }
}

// ---------------- K4: column stats of G ------------------------------------
__global__ __launch_bounds__(256) void k_colstatsG() {
    int col = threadIdx.x & 63, rg = threadIdx.x >> 6;
    int r0 = blockIdx.x * 256;
    double s = 0.0, q = 0.0;
    for (int r = rg; r < 256; r += 4) {
        float v = d_G[(size_t)(r0 + r) * 64 + col];
        s += (double)v; q += (double)v * (double)v;
    }
    __shared__ double sh[256], shq[256];
    sh[threadIdx.x] = s; shq[threadIdx.x] = q;
    __syncthreads();
    if (rg == 0) {
#pragma unroll
        for (int g = 1; g < 4; g++) { s += sh[col + 64 * g]; q += shq[col + 64 * g]; }
        atomicAdd(&d_s1[col], s);
        atomicAdd(&d_q1[col], q);
    }
}

// ---------------- K5: layer-1 BN+ReLU -> h1 @ W_enc + b_enc (+stats) -------
__global__ __launch_bounds__(256) void k_mlp2(const float* __restrict__ g1,
                                              const float* __restrict__ bt1,
                                              const float* __restrict__ Wenc,
                                              const float* __restrict__ benc) {
    __shared__ float mu1[64], sc1[64], bts[64];
    __shared__ float We[64 * 32];
    __shared__ float be[32];
    __shared__ float h1buf[8][64];
    int tid = threadIdx.x;
    if (tid < 64) {
        double tot = d_nsum[0], totq = d_nsum[1];
        double sigma2 = (totq - tot * tot / BD_TOT) / (BD_TOT - 1.0);
        double mu  = d_s1[tid] / 16384.0;
        double var = d_q1[tid] / 16384.0 - mu * mu;
        mu1[tid] = (float)mu;
        sc1[tid] = g1[tid] * (float)rsqrt(var + 1e-5 * sigma2);
        bts[tid] = bt1[tid];
    }
    for (int i = tid; i < 64 * 32; i += 256) We[i] = Wenc[i];
    if (tid < 32) be[tid] = benc[tid];
    __syncthreads();

    int w = tid >> 5, lane = tid & 31;
    int rbase = blockIdx.x * 64 + w * 8;
    float ls = 0.f, lq = 0.f;
    for (int rr = 0; rr < 8; rr++) {
        int row = rbase + rr;
        float a0 = d_G[(size_t)row * 64 + lane];
        float a1 = d_G[(size_t)row * 64 + 32 + lane];
        h1buf[w][lane]      = fmaxf(fmaf(a0 - mu1[lane],      sc1[lane],      bts[lane]),      0.f);
        h1buf[w][32 + lane] = fmaxf(fmaf(a1 - mu1[32 + lane], sc1[32 + lane], bts[32 + lane]), 0.f);
        __syncwarp();
        float acc = be[lane];
#pragma unroll
        for (int k = 0; k < 64; k++) acc = fmaf(h1buf[w][k], We[k * 32 + lane], acc);
        d_H2[(size_t)row * 32 + lane] = acc;
        ls += acc; lq += acc * acc;
        __syncwarp();
    }
    atomicAdd(&d_s2[lane], (double)ls);
    atomicAdd(&d_q2[lane], (double)lq);
}

// ---------------- K6: layer-2 BN+ReLU -> h2 @ W_dec + b_dec (+stats) -------
__global__ __launch_bounds__(256) void k_mlp3(const float* __restrict__ g2,
                                              const float* __restrict__ bt2,
                                              const float* __restrict__ Wdec,
                                              const float* __restrict__ bdec) {
    __shared__ float mu2[32], sc2[32], bts[32];
    __shared__ float Wd[32 * 64];
    __shared__ float bd[64];
    __shared__ float h2buf[8][32];
    int tid = threadIdx.x;
    if (tid < 32) {
        double mu  = d_s2[tid] / 16384.0;
        double var = d_q2[tid] / 16384.0 - mu * mu;
        mu2[tid] = (float)mu;
        sc2[tid] = g2[tid] * (float)rsqrt(var + 1e-5);
        bts[tid] = bt2[tid];
    }
    for (int i = tid; i < 32 * 64; i += 256) Wd[i] = Wdec[i];
    if (tid < 64) bd[tid] = bdec[tid];
    __syncthreads();

    int w = tid >> 5, lane = tid & 31;
    int rbase = blockIdx.x * 64 + w * 8;
    float ls0 = 0.f, lq0 = 0.f, ls1 = 0.f, lq1 = 0.f;
    for (int rr = 0; rr < 8; rr++) {
        int row = rbase + rr;
        float v = d_H2[(size_t)row * 32 + lane];
        h2buf[w][lane] = fmaxf(fmaf(v - mu2[lane], sc2[lane], bts[lane]), 0.f);
        __syncwarp();
        float acc0 = bd[lane], acc1 = bd[32 + lane];
#pragma unroll
        for (int k = 0; k < 32; k++) {
            float h = h2buf[w][k];
            acc0 = fmaf(h, Wd[k * 64 + lane],      acc0);
            acc1 = fmaf(h, Wd[k * 64 + 32 + lane], acc1);
        }
        d_H3[(size_t)row * 64 + lane]      = acc0;
        d_H3[(size_t)row * 64 + 32 + lane] = acc1;
        ls0 += acc0; lq0 += acc0 * acc0;
        ls1 += acc1; lq1 += acc1 * acc1;
        __syncwarp();
    }
    atomicAdd(&d_s3[lane],      (double)ls0);
    atomicAdd(&d_q3[lane],      (double)lq0);
    atomicAdd(&d_s3[32 + lane], (double)lq1 * 0.0 + (double)ls1);
    atomicAdd(&d_q3[32 + lane], (double)lq1);
}

// ---------------- K7: BN3+ReLU -> h3 @ {W_pi,W_m,W_th} + act (tf32 MMA) ----
// BM=128 x BN=128 tile, K=64 fully resident. 8 warps: 4(M) x 2(N).
// Each warp: 32(M) x 64(N) = 2 m-tiles x 8 n-tiles of m16n8k8.
#define AH_LD 68
#define WS_LD 136
__global__ __launch_bounds__(256, 2) void k_out(const float* __restrict__ g3,
                                                const float* __restrict__ bt3,
                                                const float* __restrict__ Wpi,
                                                const float* __restrict__ bpi,
                                                const float* __restrict__ Wm,
                                                const float* __restrict__ bm,
                                                const float* __restrict__ Wth,
                                                const float* __restrict__ bth,
                                                float* __restrict__ out) {
    extern __shared__ u32 smu[];
    u32*   Ah  = smu;                       // 128 x 68
    u32*   Wsm = smu + 128 * AH_LD;         // 64 x 136
    float* mu3 = (float*)(smu + 128 * AH_LD + 64 * WS_LD);
    float* sc3 = mu3 + 64;
    float* bts = sc3 + 64;
    float* bs  = bts + 64;                  // 128

    int tid = threadIdx.x;
    int mz  = blockIdx.z;
    const float* W  = (mz == 0) ? Wpi : ((mz == 1) ? Wm : Wth);
    const float* bb = (mz == 0) ? bpi : ((mz == 1) ? bm : bth);
    int c0 = blockIdx.x * 128, r0 = blockIdx.y * 128;

    if (tid < 64) {
        double mu  = d_s3[tid] / 16384.0;
        double var = d_q3[tid] / 16384.0 - mu * mu;
        mu3[tid] = (float)mu;
        sc3[tid] = g3[tid] * (float)rsqrt(var + 1e-5);
        bts[tid] = bt3[tid];
    }
    if (tid < 128) bs[tid] = bb[c0 + tid];
    __syncthreads();

    {   // load h3 tile 128x64 (BN+ReLU+tf32), 32 floats per thread
        int lr = tid >> 1, cb = (tid & 1) * 32;
        const float4* src = (const float4*)&d_H3[(size_t)(r0 + lr) * 64 + cb];
        u32* dst = Ah + lr * AH_LD + cb;
#pragma unroll
        for (int j = 0; j < 8; j++) {
            float4 v = src[j];
            int c = cb + j * 4;
            uint4 o;
            o.x = to_tf32(fmaxf(fmaf(v.x - mu3[c + 0], sc3[c + 0], bts[c + 0]), 0.f));
            o.y = to_tf32(fmaxf(fmaf(v.y - mu3[c + 1], sc3[c + 1], bts[c + 1]), 0.f));
            o.z = to_tf32(fmaxf(fmaf(v.z - mu3[c + 2], sc3[c + 2], bts[c + 2]), 0.f));
            o.w = to_tf32(fmaxf(fmaf(v.w - mu3[c + 3], sc3[c + 3], bts[c + 3]), 0.f));
            *(uint4*)(dst + j * 4) = o;
        }
        // load W tile 64x128 (tf32), 32 floats per thread
        int kr = tid >> 2, wb = (tid & 3) * 32;
        const float* wsrc = &W[(size_t)kr * 4096 + c0 + wb];
        u32* wdst = Wsm + kr * WS_LD + wb;
#pragma unroll
        for (int j = 0; j < 8; j++) {
            float4 v = *(const float4*)(wsrc + j * 4);
            uint4 o;
            o.x = to_tf32(v.x); o.y = to_tf32(v.y);
            o.z = to_tf32(v.z); o.w = to_tf32(v.w);
            *(uint4*)(wdst + j * 4) = o;
        }
    }
    __syncthreads();

    int warp = tid >> 5, lane = tid & 31;
    int wm = warp >> 1, wn = warp & 1;
    int g = lane >> 2, t = lane & 3;
    int arow0 = wm * 32 + g;
    int bcol0 = wn * 64 + g;

    float cfr[2][8][4];
#pragma unroll
    for (int mt = 0; mt < 2; mt++)
#pragma unroll
        for (int nt = 0; nt < 8; nt++)
#pragma unroll
            for (int i = 0; i < 4; i++) cfr[mt][nt][i] = 0.f;

#pragma unroll
    for (int kt = 0; kt < 8; kt++) {
        int k0 = kt * 8;
        u32 bfr[8][2];
#pragma unroll
        for (int nt = 0; nt < 8; nt++) {
            bfr[nt][0] = Wsm[(k0 + t) * WS_LD + bcol0 + nt * 8];
            bfr[nt][1] = Wsm[(k0 + t + 4) * WS_LD + bcol0 + nt * 8];
        }
        u32 afr[2][4];
#pragma unroll
        for (int mt = 0; mt < 2; mt++) {
            int r = arow0 + mt * 16;
            afr[mt][0] = Ah[r * AH_LD + k0 + t];
            afr[mt][1] = Ah[(r + 8) * AH_LD + k0 + t];
            afr[mt][2] = Ah[r * AH_LD + k0 + t + 4];
            afr[mt][3] = Ah[(r + 8) * AH_LD + k0 + t + 4];
        }
#pragma unroll
        for (int mt = 0; mt < 2; mt++)
#pragma unroll
            for (int nt = 0; nt < 8; nt++)
                mma1688(cfr[mt][nt], afr[mt], bfr[nt]);
    }

    size_t obase = (size_t)mz * (size_t)B_ROWS * D_COLS + (size_t)r0 * D_COLS + c0;
#pragma unroll
    for (int mt = 0; mt < 2; mt++) {
        int rA = wm * 32 + mt * 16 + g;
        int rB = rA + 8;
#pragma unroll
        for (int nt = 0; nt < 8; nt++) {
            int lc = wn * 64 + nt * 8 + t * 2;
            float z0 = cfr[mt][nt][0] + bs[lc];
            float z1 = cfr[mt][nt][1] + bs[lc + 1];
            float z2 = cfr[mt][nt][2] + bs[lc];
            float z3 = cfr[mt][nt][3] + bs[lc + 1];
            if (mz == 0) {
                z0 = __fdividef(1.f, 1.f + __expf(-z0));
                z1 = __fdividef(1.f, 1.f + __expf(-z1));
                z2 = __fdividef(1.f, 1.f + __expf(-z2));
                z3 = __fdividef(1.f, 1.f + __expf(-z3));
            } else {
                z0 = __expf(z0); z1 = __expf(z1);
                z2 = __expf(z2); z3 = __expf(z3);
            }
            *(float2*)&out[obase + (size_t)rA * D_COLS + lc] = make_float2(z0, z1);
            *(float2*)&out[obase + (size_t)rB * D_COLS + lc] = make_float2(z2, z3);
        }
    }
}

// ---------------- launch ----------------------------------------------------
extern "C" void kernel_launch(void* const* d_in, const int* in_sizes, int n_in,
                              void* d_out, int out_size) {
    const float* x    = (const float*)d_in[0];
    const float* Win  = (const float*)d_in[1];
    const float* g1   = (const float*)d_in[3];
    const float* bt1  = (const float*)d_in[4];
    const float* Wenc = (const float*)d_in[5];
    const float* benc = (const float*)d_in[6];
    const float* g2   = (const float*)d_in[7];
    const float* bt2  = (const float*)d_in[8];
    const float* Wdec = (const float*)d_in[9];
    const float* bdec = (const float*)d_in[10];
    const float* g3   = (const float*)d_in[11];
    const float* bt3  = (const float*)d_in[12];
    const float* Wpi  = (const float*)d_in[13];
    const float* bpi  = (const float*)d_in[14];
    const float* Wm   = (const float*)d_in[15];
    const float* bm   = (const float*)d_in[16];
    const float* Wth  = (const float*)d_in[17];
    const float* bth  = (const float*)d_in[18];
    float* out = (float*)d_out;

    const int koutSmem = (128 * AH_LD + 64 * WS_LD) * 4 + (64 * 3 + 128) * 4;

    cudaFuncSetAttribute(k_median, cudaFuncAttributeMaxDynamicSharedMemorySize, 65536);
    cudaFuncSetAttribute(k_out,    cudaFuncAttributeMaxDynamicSharedMemorySize, koutSmem);

    k_zero<<<1, 64>>>();
    k_rowsum<<<B_ROWS, 256>>>(x);
    k_median<<<1, 1024, 65536>>>();
    k_gemm1<<<B_ROWS / 32, 128>>>(x, Win);
    k_colstatsG<<<64, 256>>>();
    k_mlp2<<<B_ROWS / 64, 256>>>(g1, bt1, Wenc, benc);
    k_mlp3<<<B_ROWS / 64, 256>>>(g2, bt2, Wdec, bdec);
    dim3 g(D_COLS / 128, B_ROWS / 128, 3);
    k_out<<<g, 256, koutSmem>>>(g3, bt3, Wpi, bpi, Wm, bm, Wth, bth, out);
}